// round 13
// baseline (speedup 1.0000x reference)
#include <cuda_runtime.h>
#include <cuda_fp16.h>
#include <cstdint>

#define BATCH 2
#define CCH   256
#define NPIX  4096      // 64*64
#define BA    8         // BATCH*AREA
#define NA    1024      // NPIX/AREA
#define NH    8
#define HD    32
#define EPS   1e-5f

// scale * log2(e) folded into W_q rows so P = exp2(S - SHIFT)
#define QSCALE (0.17677669529663687f * 1.4426950408889634f)
#define ESHIFT 8.0f
#define H2ONES 0x3C003C00u

// Scratch (device globals; no allocation allowed)
__device__ __half g_Qh[BA * NH * NA * HD];    // [bh][i][d]  pre-scaled fp16
__device__ __half g_Kh[BA * NH * NA * HD];    // [bh][j][d]  fp16
__device__ __half g_Vh[BA * NH * HD * NA];    // [bh][d][j]  TRANSPOSED fp16
__device__ __half g_AOh[BATCH * NPIX * CCH];  // [b][n][c]   fp16
__device__ __half g_xh[BATCH * CCH * NPIX];   // [b][c][n]   fp16
__device__ __half g_Wh[768 * 256];            // BN-folded w_qk (Q rows xQSCALE) + w_v
__device__ __half g_Whp[256 * 256];           // BN-folded w_p
__device__ float  g_sh[768];
__device__ float  g_shp[256];

// ---------------------------------------------------------------------------
// PTX helpers
// ---------------------------------------------------------------------------
__device__ __forceinline__ void mma16816(float& c0, float& c1, float& c2, float& c3,
                                         uint32_t a0, uint32_t a1, uint32_t a2, uint32_t a3,
                                         uint32_t b0, uint32_t b1)
{
    asm volatile(
        "mma.sync.aligned.m16n8k16.row.col.f32.f16.f16.f32 "
        "{%0,%1,%2,%3}, {%4,%5,%6,%7}, {%8,%9}, {%0,%1,%2,%3};"
        : "+f"(c0), "+f"(c1), "+f"(c2), "+f"(c3)
        : "r"(a0), "r"(a1), "r"(a2), "r"(a3), "r"(b0), "r"(b1));
}

__device__ __forceinline__ uint32_t pack_h2(float lo, float hi) {
    uint32_t r;
    asm("cvt.rn.f16x2.f32 %0, %1, %2;" : "=r"(r) : "f"(hi), "f"(lo));
    return r;
}

// two exp2 in one MUFU op, result stays packed fp16x2
__device__ __forceinline__ uint32_t h2ex2(uint32_t x) {
    uint32_t r;
    asm("ex2.approx.f16x2 %0, %1;" : "=r"(r) : "r"(x));
    return r;
}

__device__ __forceinline__ uint32_t cvta_sh(const void* p) {
    return (uint32_t)__cvta_generic_to_shared(p);
}

__device__ __forceinline__ void cp16(void* sm, const void* gm) {
    asm volatile("cp.async.cg.shared.global [%0], [%1], 16;"
        :: "r"(cvta_sh(sm)), "l"(gm));
}
#define CP_COMMIT() asm volatile("cp.async.commit_group;")
#define CP_WAIT(n)  asm volatile("cp.async.wait_group %0;" :: "n"(n))

#define LDMX4(r0,r1,r2,r3,addr) \
    asm volatile("ldmatrix.sync.aligned.m8n8.x4.shared.b16 {%0,%1,%2,%3}, [%4];" \
        : "=r"(r0),"=r"(r1),"=r"(r2),"=r"(r3) : "r"(addr))
#define LDMX4T(r0,r1,r2,r3,addr) \
    asm volatile("ldmatrix.sync.aligned.m8n8.x4.trans.shared.b16 {%0,%1,%2,%3}, [%4];" \
        : "=r"(r0),"=r"(r1),"=r"(r2),"=r"(r3) : "r"(addr))

// ---------------------------------------------------------------------------
// Prepass: fold BN into weights, convert to fp16; compute shift vectors.
// ---------------------------------------------------------------------------
__global__ void prep_w(
    const float* __restrict__ w_qk, const float* __restrict__ g_qk, const float* __restrict__ b_qk,
    const float* __restrict__ m_qk, const float* __restrict__ v_qk,
    const float* __restrict__ w_v,  const float* __restrict__ g_v,  const float* __restrict__ b_v,
    const float* __restrict__ m_v,  const float* __restrict__ v_v,
    const float* __restrict__ w_p,  const float* __restrict__ g_p,  const float* __restrict__ b_p,
    const float* __restrict__ m_p,  const float* __restrict__ v_p)
{
    const int row = blockIdx.x;
    const int c   = threadIdx.x;
    const float *w, *g, *b, *m, *v;
    __half* dst; float* shd;
    int r; float extra = 1.f;
    if (row < 512) {
        w = w_qk; g = g_qk; b = b_qk; m = m_qk; v = v_qk;
        r = row; dst = g_Wh + (size_t)row * 256; shd = g_sh + row;
        if (row < 256) extra = QSCALE;
    } else if (row < 768) {
        w = w_v; g = g_v; b = b_v; m = m_v; v = v_v;
        r = row - 512; dst = g_Wh + (size_t)row * 256; shd = g_sh + row;
    } else {
        w = w_p; g = g_p; b = b_p; m = m_p; v = v_p;
        r = row - 768; dst = g_Whp + (size_t)r * 256; shd = g_shp + r;
    }
    float s0 = g[r] * rsqrtf(v[r] + EPS);
    dst[c] = __float2half_rn(w[(size_t)r * 256 + c] * s0 * extra);
    if (c == 0) *shd = (b[r] - m[r] * s0) * extra;
}

__global__ void prep_x(const float* __restrict__ x)
{
    const int i = (blockIdx.x * 256 + threadIdx.x) * 4;
    float4 v = *(const float4*)(x + i);
    __half2* d = (__half2*)(g_xh + i);
    d[0] = __floats2half2_rn(v.x, v.y);
    d[1] = __floats2half2_rn(v.z, v.w);
}

// ---------------------------------------------------------------------------
// proj_in via mma.sync: Y[o,n] = Wh[o,:] . xh[b,:,n] + sh[o], o in [0,768)
// ---------------------------------------------------------------------------
__global__ __launch_bounds__(256) void proj_in_mma()
{
    __shared__ __align__(16) __half Ws[128][72];
    __shared__ __align__(16) __half Xs[64][72];

    const int b  = blockIdx.z;
    const int o0 = blockIdx.y * 128;
    const int n0 = blockIdx.x * 64;
    const int t    = threadIdx.x;
    const int lane = t & 31, wid = t >> 5;
    const int wo = wid >> 1, wn = wid & 1;
    const int gr = lane >> 2, tg = lane & 3;

    const __half* xb = g_xh + (size_t)b * CCH * NPIX;

    float acc[2][4][4];
    #pragma unroll
    for (int i = 0; i < 2; i++)
        #pragma unroll
        for (int j = 0; j < 4; j++)
            #pragma unroll
            for (int k = 0; k < 4; k++) acc[i][j][k] = 0.f;

    for (int k0 = 0; k0 < 256; k0 += 64) {
        if (k0) __syncthreads();
        #pragma unroll
        for (int u = 0; u < 4; u++) {
            int idx = t + u * 256;
            int row = idx >> 3, seg = idx & 7;
            *(uint4*)&Ws[row][seg * 8] =
                *(const uint4*)(g_Wh + (size_t)(o0 + row) * 256 + k0 + seg * 8);
        }
        #pragma unroll
        for (int u = 0; u < 2; u++) {
            int idx = t + u * 256;
            int row = idx >> 3, seg = idx & 7;
            *(uint4*)&Xs[row][seg * 8] =
                *(const uint4*)(xb + (size_t)(k0 + row) * NPIX + n0 + seg * 8);
        }
        __syncthreads();

        #pragma unroll
        for (int k16 = 0; k16 < 4; k16++) {
            uint32_t a[2][4];
            #pragma unroll
            for (int ot = 0; ot < 2; ot++) {
                uint32_t addr = cvta_sh(&Ws[wo * 32 + ot * 16 + (lane & 15)]
                                           [k16 * 16 + ((lane >> 4) << 3)]);
                LDMX4(a[ot][0], a[ot][1], a[ot][2], a[ot][3], addr);
            }
            uint32_t bf[2][4];
            #pragma unroll
            for (int nt = 0; nt < 2; nt++) {
                uint32_t addr = cvta_sh(&Xs[k16 * 16 + (lane & 15)]
                                           [wn * 32 + nt * 16 + ((lane >> 4) << 3)]);
                LDMX4T(bf[nt][0], bf[nt][1], bf[nt][2], bf[nt][3], addr);
            }
            #pragma unroll
            for (int ot = 0; ot < 2; ot++)
                #pragma unroll
                for (int nt = 0; nt < 2; nt++)
                    #pragma unroll
                    for (int nh = 0; nh < 2; nh++) {
                        int ni = nt * 2 + nh;
                        mma16816(acc[ot][ni][0], acc[ot][ni][1], acc[ot][ni][2], acc[ot][ni][3],
                                 a[ot][0], a[ot][1], a[ot][2], a[ot][3],
                                 bf[nt][nh * 2], bf[nt][nh * 2 + 1]);
                    }
        }
    }

    #pragma unroll
    for (int ot = 0; ot < 2; ot++) {
        const int og = o0 + wo * 32 + ot * 16 + gr;
        const float sh0 = g_sh[og], sh1 = g_sh[og + 8];
        if (o0 < 512) {
            __half* dst = (o0 < 256) ? g_Qh : g_Kh;
            const int ob0 = og & 255, ob1 = (og + 8) & 255;
            const int h0 = ob0 >> 5, d0 = ob0 & 31;
            const int h1 = ob1 >> 5, d1 = ob1 & 31;
            #pragma unroll
            for (int ni = 0; ni < 4; ni++) {
                int n  = n0 + wn * 32 + (ni >> 1) * 16 + (ni & 1) * 8 + 2 * tg;
                int ba = b * 4 + (n >> 10), na = n & 1023;
                size_t base = (size_t)(ba * NH) * NA * HD;
                dst[base + ((size_t)h0 * NA + na    ) * HD + d0] = __float2half_rn(acc[ot][ni][0] + sh0);
                dst[base + ((size_t)h0 * NA + na + 1) * HD + d0] = __float2half_rn(acc[ot][ni][1] + sh0);
                dst[base + ((size_t)h1 * NA + na    ) * HD + d1] = __float2half_rn(acc[ot][ni][2] + sh1);
                dst[base + ((size_t)h1 * NA + na + 1) * HD + d1] = __float2half_rn(acc[ot][ni][3] + sh1);
            }
        } else {
            const int oc0 = og - 512, oc1 = og - 512 + 8;
            const int h0 = oc0 >> 5, d0 = oc0 & 31;
            const int h1 = oc1 >> 5, d1 = oc1 & 31;
            #pragma unroll
            for (int ni = 0; ni < 4; ni++) {
                int n  = n0 + wn * 32 + (ni >> 1) * 16 + (ni & 1) * 8 + 2 * tg;
                int ba = b * 4 + (n >> 10), na = n & 1023;
                *(__half2*)&g_Vh[(((size_t)(ba * NH + h0)) * HD + d0) * NA + na] =
                    __floats2half2_rn(acc[ot][ni][0] + sh0, acc[ot][ni][1] + sh0);
                *(__half2*)&g_Vh[(((size_t)(ba * NH + h1)) * HD + d1) * NA + na] =
                    __floats2half2_rn(acc[ot][ni][2] + sh1, acc[ot][ni][3] + sh1);
            }
        }
    }
}

// ---------------------------------------------------------------------------
// Attention v6: 16 q rows/warp -> 4096 total warps (2x) for latency hiding.
// 256-thread CTAs (8 warps, 128 q rows), 64-row KV chunks (19.4KB smem),
// reg cap 85 via launch_bounds(256,3) -> 3 CTAs/SM = 24 warps.
// ldmatrix frags, cp.async double buffer, shift folded into S acc,
// f16x2 exp2, row sums via ones-MMA. Grid (8, 64).
// ---------------------------------------------------------------------------
__global__ __launch_bounds__(256, 3) void attn_mma()
{
    __shared__ __align__(16) unsigned char Ks[2][64 * 80];    // [j][d]  pitch 80
    __shared__ __align__(16) unsigned char Vs[2][32 * 144];   // [d][j]  pitch 144

    const int t    = threadIdx.x;
    const int wid  = t >> 5;
    const int lane = t & 31;
    const int gr   = lane >> 2;
    const int tg   = lane & 3;
    const int bh   = blockIdx.y;
    const int q0   = blockIdx.x * 128;
    const int i0   = q0 + wid * 16;

    const __half* Qg = g_Qh + ((size_t)bh * NA + i0) * HD;
    const __half* Kg = g_Kh + (size_t)bh * NA * HD;
    const __half* Vg = g_Vh + (size_t)bh * HD * NA;

    // Q A-fragments: 2 k-tiles
    uint32_t qa[2][4];
    #pragma unroll
    for (int kt = 0; kt < 2; kt++) {
        qa[kt][0] = *(const uint32_t*)(Qg + (gr    ) * HD + kt * 16 + 2 * tg    );
        qa[kt][1] = *(const uint32_t*)(Qg + (gr + 8) * HD + kt * 16 + 2 * tg    );
        qa[kt][2] = *(const uint32_t*)(Qg + (gr    ) * HD + kt * 16 + 2 * tg + 8);
        qa[kt][3] = *(const uint32_t*)(Qg + (gr + 8) * HD + kt * 16 + 2 * tg + 8);
    }

    float o[4][4];
    #pragma unroll
    for (int dt = 0; dt < 4; dt++)
        #pragma unroll
        for (int c = 0; c < 4; c++) o[dt][c] = 0.f;
    float lacc[4] = {0.f, 0.f, 0.f, 0.f};

    // stage tile 0 into buf 0 (256 threads: 1 cp16 each per tile)
    {
        int row = t >> 2, part = t & 3;
        cp16(&Ks[0][row * 80 + part * 16], Kg + (size_t)row * HD + part * 8);
        int vrow = t >> 3, vpart = t & 7;
        cp16(&Vs[0][vrow * 144 + vpart * 16], Vg + (size_t)vrow * NA + vpart * 8);
        CP_COMMIT();
    }

    #pragma unroll 1
    for (int it = 0; it < 16; it++) {
        const int buf = it & 1;
        if (it < 15) {
            const int j0 = (it + 1) * 64, nb = buf ^ 1;
            int row = t >> 2, part = t & 3;
            cp16(&Ks[nb][row * 80 + part * 16], Kg + (size_t)(j0 + row) * HD + part * 8);
            int vrow = t >> 3, vpart = t & 7;
            cp16(&Vs[nb][vrow * 144 + vpart * 16], Vg + (size_t)vrow * NA + j0 + vpart * 8);
            CP_COMMIT();
            CP_WAIT(1);
        } else {
            CP_WAIT(0);
        }
        __syncthreads();

        #pragma unroll
        for (int m = 0; m < 4; m++) {
            // K fragments: 2 ldmatrix.x4
            uint32_t kf[2][4];
            {
                uint32_t a0 = cvta_sh(&Ks[buf][(m * 16 + (lane & 7)) * 80 + (lane >> 3) * 16]);
                LDMX4(kf[0][0], kf[0][1], kf[0][2], kf[0][3], a0);
                LDMX4(kf[1][0], kf[1][1], kf[1][2], kf[1][3], a0 + 8 * 80);
            }

            // S = Q.K^T - ESHIFT (shift folded into accumulator init)
            float s[2][4];
            #pragma unroll
            for (int h = 0; h < 2; h++) {
                float c0 = -ESHIFT, c1 = -ESHIFT, c2 = -ESHIFT, c3 = -ESHIFT;
                mma16816(c0, c1, c2, c3,
                         qa[0][0], qa[0][1], qa[0][2], qa[0][3],
                         kf[h][0], kf[h][1]);
                mma16816(c0, c1, c2, c3,
                         qa[1][0], qa[1][1], qa[1][2], qa[1][3],
                         kf[h][2], kf[h][3]);
                s[h][0] = c0; s[h][1] = c1; s[h][2] = c2; s[h][3] = c3;
            }

            // pack then f16x2 exp2 -> P fragments directly
            uint32_t pa[4];
            pa[0] = h2ex2(pack_h2(s[0][0], s[0][1]));
            pa[1] = h2ex2(pack_h2(s[0][2], s[0][3]));
            pa[2] = h2ex2(pack_h2(s[1][0], s[1][1]));
            pa[3] = h2ex2(pack_h2(s[1][2], s[1][3]));

            // row sums: lacc += P . ones  (tensor pipe, no scalar adds)
            mma16816(lacc[0], lacc[1], lacc[2], lacc[3],
                     pa[0], pa[1], pa[2], pa[3], H2ONES, H2ONES);

            // V fragments: 2 ldmatrix.x4
            uint32_t vf[4][2];
            {
                uint32_t a0 = cvta_sh(&Vs[buf][(((lane >> 4) << 3) + (lane & 7)) * 144
                                               + m * 32 + ((lane >> 3) & 1) * 16]);
                LDMX4(vf[0][0], vf[0][1], vf[1][0], vf[1][1], a0);
                LDMX4(vf[2][0], vf[2][1], vf[3][0], vf[3][1], a0 + 16 * 144);
            }

            // O += P.V
            #pragma unroll
            for (int dt = 0; dt < 4; dt++)
                mma16816(o[dt][0], o[dt][1], o[dt][2], o[dt][3],
                         pa[0], pa[1], pa[2], pa[3],
                         vf[dt][0], vf[dt][1]);
        }
        __syncthreads();
    }

    // ---- normalize + write AO[b][n][c] fp16 (row sums already per-thread) ----
    const int b = bh >> 5, area = (bh >> 3) & 3, h = bh & 7;
    const float inv0 = 1.f / lacc[0];
    const float inv1 = 1.f / lacc[2];
    const int nb = area * NA + i0;
    __half* outp = g_AOh + ((size_t)b * NPIX + nb) * CCH + h * HD;
    #pragma unroll
    for (int dt = 0; dt < 4; dt++) {
        *(__half2*)(outp + (size_t)(gr    ) * CCH + dt * 8 + 2 * tg) =
            __floats2half2_rn(o[dt][0] * inv0, o[dt][1] * inv0);
        *(__half2*)(outp + (size_t)(gr + 8) * CCH + dt * 8 + 2 * tg) =
            __floats2half2_rn(o[dt][2] * inv1, o[dt][3] * inv1);
    }
}

// ---------------------------------------------------------------------------
// proj_out via mma.sync: out[b,co,n] = Whp[co,:] . AOh[b,n,:] + shp[co]
// ---------------------------------------------------------------------------
__global__ __launch_bounds__(256) void proj_out_mma(float* __restrict__ out)
{
    __shared__ __align__(16) __half Ws[128][72];
    __shared__ __align__(16) __half As[64][72];

    const int b   = blockIdx.z;
    const int co0 = blockIdx.y * 128;
    const int n0  = blockIdx.x * 64;
    const int t    = threadIdx.x;
    const int lane = t & 31, wid = t >> 5;
    const int wo = wid >> 1, wn = wid & 1;
    const int gr = lane >> 2, tg = lane & 3;

    const __half* ab = g_AOh + (size_t)b * NPIX * CCH;

    float acc[2][4][4];
    #pragma unroll
    for (int i = 0; i < 2; i++)
        #pragma unroll
        for (int j = 0; j < 4; j++)
            #pragma unroll
            for (int k = 0; k < 4; k++) acc[i][j][k] = 0.f;

    for (int k0 = 0; k0 < 256; k0 += 64) {
        if (k0) __syncthreads();
        #pragma unroll
        for (int u = 0; u < 4; u++) {
            int idx = t + u * 256;
            int row = idx >> 3, seg = idx & 7;
            *(uint4*)&Ws[row][seg * 8] =
                *(const uint4*)(g_Whp + (size_t)(co0 + row) * 256 + k0 + seg * 8);
        }
        #pragma unroll
        for (int u = 0; u < 2; u++) {
            int idx = t + u * 256;
            int row = idx >> 3, seg = idx & 7;
            *(uint4*)&As[row][seg * 8] =
                *(const uint4*)(ab + (size_t)(n0 + row) * CCH + k0 + seg * 8);
        }
        __syncthreads();

        #pragma unroll
        for (int k16 = 0; k16 < 4; k16++) {
            uint32_t a[2][4];
            #pragma unroll
            for (int ot = 0; ot < 2; ot++) {
                uint32_t addr = cvta_sh(&Ws[wo * 32 + ot * 16 + (lane & 15)]
                                           [k16 * 16 + ((lane >> 4) << 3)]);
                LDMX4(a[ot][0], a[ot][1], a[ot][2], a[ot][3], addr);
            }
            uint32_t bf[2][4];
            #pragma unroll
            for (int nt = 0; nt < 2; nt++) {
                uint32_t addr = cvta_sh(&As[wn * 32 + nt * 16 + ((lane >> 4) << 3) + (lane & 7)]
                                           [k16 * 16 + (lane & 8)]);
                LDMX4(bf[nt][0], bf[nt][1], bf[nt][2], bf[nt][3], addr);
            }
            #pragma unroll
            for (int ot = 0; ot < 2; ot++)
                #pragma unroll
                for (int nt = 0; nt < 2; nt++)
                    #pragma unroll
                    for (int nh = 0; nh < 2; nh++) {
                        int ni = nt * 2 + nh;
                        mma16816(acc[ot][ni][0], acc[ot][ni][1], acc[ot][ni][2], acc[ot][ni][3],
                                 a[ot][0], a[ot][1], a[ot][2], a[ot][3],
                                 bf[nt][nh * 2], bf[nt][nh * 2 + 1]);
                    }
        }
    }

    #pragma unroll
    for (int ot = 0; ot < 2; ot++) {
        const int co = co0 + wo * 32 + ot * 16 + gr;
        const float sh0 = g_shp[co], sh1 = g_shp[co + 8];
        #pragma unroll
        for (int ni = 0; ni < 4; ni++) {
            int n = n0 + wn * 32 + (ni >> 1) * 16 + (ni & 1) * 8 + 2 * tg;
            float2 r0, r1;
            r0.x = acc[ot][ni][0] + sh0; r0.y = acc[ot][ni][1] + sh0;
            r1.x = acc[ot][ni][2] + sh1; r1.y = acc[ot][ni][3] + sh1;
            *(float2*)(out + ((size_t)(b * CCH + co    )) * NPIX + n) = r0;
            *(float2*)(out + ((size_t)(b * CCH + co + 8)) * NPIX + n) = r1;
        }
    }
}

// ---------------------------------------------------------------------------
extern "C" void kernel_launch(void* const* d_in, const int* in_sizes, int n_in,
                              void* d_out, int out_size)
{
    const float* x    = (const float*)d_in[0];
    const float* w_qk = (const float*)d_in[1];
    const float* g_qk = (const float*)d_in[2];
    const float* b_qk = (const float*)d_in[3];
    const float* m_qk = (const float*)d_in[4];
    const float* v_qk = (const float*)d_in[5];
    const float* w_v  = (const float*)d_in[6];
    const float* g_v  = (const float*)d_in[7];
    const float* b_v  = (const float*)d_in[8];
    const float* m_v  = (const float*)d_in[9];
    const float* v_v  = (const float*)d_in[10];
    const float* w_p  = (const float*)d_in[11];
    const float* g_p  = (const float*)d_in[12];
    const float* b_p  = (const float*)d_in[13];
    const float* m_p  = (const float*)d_in[14];
    const float* v_p  = (const float*)d_in[15];
    float* out = (float*)d_out;

    prep_w<<<1024, 256>>>(w_qk, g_qk, b_qk, m_qk, v_qk,
                          w_v,  g_v,  b_v,  m_v,  v_v,
                          w_p,  g_p,  b_p,  m_p,  v_p);
    prep_x<<<2048, 256>>>(x);
    proj_in_mma<<<dim3(64, 6, BATCH), 256>>>();
    attn_mma<<<dim3(8, 64), 256>>>();
    proj_out_mma<<<dim3(64, 2, BATCH), 256>>>(out);
}

// round 14
// speedup vs baseline: 1.0507x; 1.0507x over previous
#include <cuda_runtime.h>
#include <cuda_fp16.h>
#include <cstdint>

#define BATCH 2
#define CCH   256
#define NPIX  4096      // 64*64
#define BA    8         // BATCH*AREA
#define NA    1024      // NPIX/AREA
#define NH    8
#define HD    32
#define EPS   1e-5f

// scale * log2(e) folded into W_q rows so P = exp2(S - SHIFT)
#define QSCALE (0.17677669529663687f * 1.4426950408889634f)
#define ESHIFT 8.0f
#define H2ONES 0x3C003C00u

// Scratch (device globals; no allocation allowed)
__device__ __half g_Qh[BA * NH * NA * HD];    // [bh][i][d]  pre-scaled fp16
__device__ __half g_Kh[BA * NH * NA * HD];    // [bh][j][d]  fp16
__device__ __half g_Vh[BA * NH * HD * NA];    // [bh][d][j]  TRANSPOSED fp16
__device__ __half g_AOh[BATCH * NPIX * CCH];  // [b][n][c]   fp16
__device__ __half g_xh[BATCH * CCH * NPIX];   // [b][c][n]   fp16
__device__ __half g_Wh[768 * 256];            // BN-folded w_qk (Q rows xQSCALE) + w_v
__device__ __half g_Whp[256 * 256];           // BN-folded w_p
__device__ float  g_sh[768];
__device__ float  g_shp[256];

// ---------------------------------------------------------------------------
// PTX helpers
// ---------------------------------------------------------------------------
__device__ __forceinline__ void mma16816(float& c0, float& c1, float& c2, float& c3,
                                         uint32_t a0, uint32_t a1, uint32_t a2, uint32_t a3,
                                         uint32_t b0, uint32_t b1)
{
    asm volatile(
        "mma.sync.aligned.m16n8k16.row.col.f32.f16.f16.f32 "
        "{%0,%1,%2,%3}, {%4,%5,%6,%7}, {%8,%9}, {%0,%1,%2,%3};"
        : "+f"(c0), "+f"(c1), "+f"(c2), "+f"(c3)
        : "r"(a0), "r"(a1), "r"(a2), "r"(a3), "r"(b0), "r"(b1));
}

__device__ __forceinline__ uint32_t pack_h2(float lo, float hi) {
    uint32_t r;
    asm("cvt.rn.f16x2.f32 %0, %1, %2;" : "=r"(r) : "f"(hi), "f"(lo));
    return r;
}

// two exp2 in one MUFU op, result stays packed fp16x2
__device__ __forceinline__ uint32_t h2ex2(uint32_t x) {
    uint32_t r;
    asm("ex2.approx.f16x2 %0, %1;" : "=r"(r) : "r"(x));
    return r;
}

__device__ __forceinline__ uint32_t cvta_sh(const void* p) {
    return (uint32_t)__cvta_generic_to_shared(p);
}

__device__ __forceinline__ void cp16(void* sm, const void* gm) {
    asm volatile("cp.async.cg.shared.global [%0], [%1], 16;"
        :: "r"(cvta_sh(sm)), "l"(gm));
}
#define CP_COMMIT() asm volatile("cp.async.commit_group;")
#define CP_WAIT(n)  asm volatile("cp.async.wait_group %0;" :: "n"(n))

#define LDMX4(r0,r1,r2,r3,addr) \
    asm volatile("ldmatrix.sync.aligned.m8n8.x4.shared.b16 {%0,%1,%2,%3}, [%4];" \
        : "=r"(r0),"=r"(r1),"=r"(r2),"=r"(r3) : "r"(addr))
#define LDMX4T(r0,r1,r2,r3,addr) \
    asm volatile("ldmatrix.sync.aligned.m8n8.x4.trans.shared.b16 {%0,%1,%2,%3}, [%4];" \
        : "=r"(r0),"=r"(r1),"=r"(r2),"=r"(r3) : "r"(addr))

// ---------------------------------------------------------------------------
// Prepass: fold BN into weights, convert to fp16; compute shift vectors.
// ---------------------------------------------------------------------------
__global__ void prep_w(
    const float* __restrict__ w_qk, const float* __restrict__ g_qk, const float* __restrict__ b_qk,
    const float* __restrict__ m_qk, const float* __restrict__ v_qk,
    const float* __restrict__ w_v,  const float* __restrict__ g_v,  const float* __restrict__ b_v,
    const float* __restrict__ m_v,  const float* __restrict__ v_v,
    const float* __restrict__ w_p,  const float* __restrict__ g_p,  const float* __restrict__ b_p,
    const float* __restrict__ m_p,  const float* __restrict__ v_p)
{
    const int row = blockIdx.x;
    const int c   = threadIdx.x;
    const float *w, *g, *b, *m, *v;
    __half* dst; float* shd;
    int r; float extra = 1.f;
    if (row < 512) {
        w = w_qk; g = g_qk; b = b_qk; m = m_qk; v = v_qk;
        r = row; dst = g_Wh + (size_t)row * 256; shd = g_sh + row;
        if (row < 256) extra = QSCALE;
    } else if (row < 768) {
        w = w_v; g = g_v; b = b_v; m = m_v; v = v_v;
        r = row - 512; dst = g_Wh + (size_t)row * 256; shd = g_sh + row;
    } else {
        w = w_p; g = g_p; b = b_p; m = m_p; v = v_p;
        r = row - 768; dst = g_Whp + (size_t)r * 256; shd = g_shp + r;
    }
    float s0 = g[r] * rsqrtf(v[r] + EPS);
    dst[c] = __float2half_rn(w[(size_t)r * 256 + c] * s0 * extra);
    if (c == 0) *shd = (b[r] - m[r] * s0) * extra;
}

__global__ void prep_x(const float* __restrict__ x)
{
    const int i = (blockIdx.x * 256 + threadIdx.x) * 4;
    float4 v = *(const float4*)(x + i);
    __half2* d = (__half2*)(g_xh + i);
    d[0] = __floats2half2_rn(v.x, v.y);
    d[1] = __floats2half2_rn(v.z, v.w);
}

// ---------------------------------------------------------------------------
// proj_in via mma.sync + cp.async double-buffered k-chunks.
// Y[o,n] = Wh[o,:] . xh[b,:,n] + sh[o], o in [0,768). CTA 128o x 64n.
// ---------------------------------------------------------------------------
__global__ __launch_bounds__(256) void proj_in_mma()
{
    __shared__ __align__(16) __half Ws[2][128][72];
    __shared__ __align__(16) __half Xs[2][64][72];

    const int b  = blockIdx.z;
    const int o0 = blockIdx.y * 128;
    const int n0 = blockIdx.x * 64;
    const int t    = threadIdx.x;
    const int lane = t & 31, wid = t >> 5;
    const int wo = wid >> 1, wn = wid & 1;
    const int gr = lane >> 2, tg = lane & 3;

    const __half* xb = g_xh + (size_t)b * CCH * NPIX;

    float acc[2][4][4];
    #pragma unroll
    for (int i = 0; i < 2; i++)
        #pragma unroll
        for (int j = 0; j < 4; j++)
            #pragma unroll
            for (int k = 0; k < 4; k++) acc[i][j][k] = 0.f;

    // stage chunk 0 into buf 0
    {
        #pragma unroll
        for (int u = 0; u < 4; u++) {
            int idx = t + u * 256;
            int row = idx >> 3, seg = idx & 7;
            cp16(&Ws[0][row][seg * 8], g_Wh + (size_t)(o0 + row) * 256 + seg * 8);
        }
        #pragma unroll
        for (int u = 0; u < 2; u++) {
            int idx = t + u * 256;
            int row = idx >> 3, seg = idx & 7;
            cp16(&Xs[0][row][seg * 8], xb + (size_t)row * NPIX + n0 + seg * 8);
        }
        CP_COMMIT();
    }

    #pragma unroll 1
    for (int it = 0; it < 4; it++) {
        const int buf = it & 1;
        if (it < 3) {
            const int k0 = (it + 1) * 64, nb = buf ^ 1;
            #pragma unroll
            for (int u = 0; u < 4; u++) {
                int idx = t + u * 256;
                int row = idx >> 3, seg = idx & 7;
                cp16(&Ws[nb][row][seg * 8], g_Wh + (size_t)(o0 + row) * 256 + k0 + seg * 8);
            }
            #pragma unroll
            for (int u = 0; u < 2; u++) {
                int idx = t + u * 256;
                int row = idx >> 3, seg = idx & 7;
                cp16(&Xs[nb][row][seg * 8], xb + (size_t)(k0 + row) * NPIX + n0 + seg * 8);
            }
            CP_COMMIT();
            CP_WAIT(1);
        } else {
            CP_WAIT(0);
        }
        __syncthreads();

        #pragma unroll
        for (int k16 = 0; k16 < 4; k16++) {
            uint32_t a[2][4];
            #pragma unroll
            for (int ot = 0; ot < 2; ot++) {
                uint32_t addr = cvta_sh(&Ws[buf][wo * 32 + ot * 16 + (lane & 15)]
                                               [k16 * 16 + ((lane >> 4) << 3)]);
                LDMX4(a[ot][0], a[ot][1], a[ot][2], a[ot][3], addr);
            }
            uint32_t bf[2][4];
            #pragma unroll
            for (int nt = 0; nt < 2; nt++) {
                uint32_t addr = cvta_sh(&Xs[buf][k16 * 16 + (lane & 15)]
                                               [wn * 32 + nt * 16 + ((lane >> 4) << 3)]);
                LDMX4T(bf[nt][0], bf[nt][1], bf[nt][2], bf[nt][3], addr);
            }
            #pragma unroll
            for (int ot = 0; ot < 2; ot++)
                #pragma unroll
                for (int nt = 0; nt < 2; nt++)
                    #pragma unroll
                    for (int nh = 0; nh < 2; nh++) {
                        int ni = nt * 2 + nh;
                        mma16816(acc[ot][ni][0], acc[ot][ni][1], acc[ot][ni][2], acc[ot][ni][3],
                                 a[ot][0], a[ot][1], a[ot][2], a[ot][3],
                                 bf[nt][nh * 2], bf[nt][nh * 2 + 1]);
                    }
        }
        __syncthreads();
    }

    #pragma unroll
    for (int ot = 0; ot < 2; ot++) {
        const int og = o0 + wo * 32 + ot * 16 + gr;
        const float sh0 = g_sh[og], sh1 = g_sh[og + 8];
        if (o0 < 512) {
            __half* dst = (o0 < 256) ? g_Qh : g_Kh;
            const int ob0 = og & 255, ob1 = (og + 8) & 255;
            const int h0 = ob0 >> 5, d0 = ob0 & 31;
            const int h1 = ob1 >> 5, d1 = ob1 & 31;
            #pragma unroll
            for (int ni = 0; ni < 4; ni++) {
                int n  = n0 + wn * 32 + (ni >> 1) * 16 + (ni & 1) * 8 + 2 * tg;
                int ba = b * 4 + (n >> 10), na = n & 1023;
                size_t base = (size_t)(ba * NH) * NA * HD;
                dst[base + ((size_t)h0 * NA + na    ) * HD + d0] = __float2half_rn(acc[ot][ni][0] + sh0);
                dst[base + ((size_t)h0 * NA + na + 1) * HD + d0] = __float2half_rn(acc[ot][ni][1] + sh0);
                dst[base + ((size_t)h1 * NA + na    ) * HD + d1] = __float2half_rn(acc[ot][ni][2] + sh1);
                dst[base + ((size_t)h1 * NA + na + 1) * HD + d1] = __float2half_rn(acc[ot][ni][3] + sh1);
            }
        } else {
            const int oc0 = og - 512, oc1 = og - 512 + 8;
            const int h0 = oc0 >> 5, d0 = oc0 & 31;
            const int h1 = oc1 >> 5, d1 = oc1 & 31;
            #pragma unroll
            for (int ni = 0; ni < 4; ni++) {
                int n  = n0 + wn * 32 + (ni >> 1) * 16 + (ni & 1) * 8 + 2 * tg;
                int ba = b * 4 + (n >> 10), na = n & 1023;
                *(__half2*)&g_Vh[(((size_t)(ba * NH + h0)) * HD + d0) * NA + na] =
                    __floats2half2_rn(acc[ot][ni][0] + sh0, acc[ot][ni][1] + sh0);
                *(__half2*)&g_Vh[(((size_t)(ba * NH + h1)) * HD + d1) * NA + na] =
                    __floats2half2_rn(acc[ot][ni][2] + sh1, acc[ot][ni][3] + sh1);
            }
        }
    }
}

// ---------------------------------------------------------------------------
// Attention (round-8 best config): 256 threads = 8 warps x 32 q rows,
// 128-row KV chunks, ldmatrix frags, cp.async double buffer, shift folded
// into S acc, f16x2 exp2, row sums via ones-MMA. Grid (4, 64).
// ---------------------------------------------------------------------------
__global__ __launch_bounds__(256) void attn_mma()
{
    __shared__ __align__(16) unsigned char Ks[2][128 * 80];   // [j][d] pitch 80
    __shared__ __align__(16) unsigned char Vs[2][32 * 272];   // [d][j] pitch 272

    const int t    = threadIdx.x;
    const int wid  = t >> 5;
    const int lane = t & 31;
    const int gr   = lane >> 2;
    const int tg   = lane & 3;
    const int bh   = blockIdx.y;
    const int q0   = blockIdx.x * 256;
    const int i0   = q0 + wid * 32;

    const __half* Qg = g_Qh + ((size_t)bh * NA + i0) * HD;
    const __half* Kg = g_Kh + (size_t)bh * NA * HD;
    const __half* Vg = g_Vh + (size_t)bh * HD * NA;

    // Q A-fragments: 2 m-tiles x 2 k-tiles
    uint32_t qa[2][2][4];
    #pragma unroll
    for (int mt = 0; mt < 2; mt++)
        #pragma unroll
        for (int kt = 0; kt < 2; kt++) {
            qa[mt][kt][0] = *(const uint32_t*)(Qg + (mt * 16 + gr    ) * HD + kt * 16 + 2 * tg    );
            qa[mt][kt][1] = *(const uint32_t*)(Qg + (mt * 16 + gr + 8) * HD + kt * 16 + 2 * tg    );
            qa[mt][kt][2] = *(const uint32_t*)(Qg + (mt * 16 + gr    ) * HD + kt * 16 + 2 * tg + 8);
            qa[mt][kt][3] = *(const uint32_t*)(Qg + (mt * 16 + gr + 8) * HD + kt * 16 + 2 * tg + 8);
        }

    float o[2][4][4];
    #pragma unroll
    for (int mt = 0; mt < 2; mt++)
        #pragma unroll
        for (int dt = 0; dt < 4; dt++)
            #pragma unroll
            for (int c = 0; c < 4; c++) o[mt][dt][c] = 0.f;
    float lacc[2][4];
    #pragma unroll
    for (int mt = 0; mt < 2; mt++)
        #pragma unroll
        for (int c = 0; c < 4; c++) lacc[mt][c] = 0.f;

    // stage tile 0 into buf 0
    {
        #pragma unroll
        for (int u = 0; u < 2; u++) {
            int idx = t + u * 256;
            int row = idx >> 2, part = idx & 3;
            cp16(&Ks[0][row * 80 + part * 16], Kg + (size_t)row * HD + part * 8);
        }
        #pragma unroll
        for (int u = 0; u < 2; u++) {
            int idx = t + u * 256;
            int row = idx >> 4, part = idx & 15;
            cp16(&Vs[0][row * 272 + part * 16], Vg + (size_t)row * NA + part * 8);
        }
        CP_COMMIT();
    }

    #pragma unroll 1
    for (int it = 0; it < 8; it++) {
        const int buf = it & 1;
        if (it < 7) {
            const int j0 = (it + 1) * 128, nb = buf ^ 1;
            #pragma unroll
            for (int u = 0; u < 2; u++) {
                int idx = t + u * 256;
                int row = idx >> 2, part = idx & 3;
                cp16(&Ks[nb][row * 80 + part * 16], Kg + (size_t)(j0 + row) * HD + part * 8);
            }
            #pragma unroll
            for (int u = 0; u < 2; u++) {
                int idx = t + u * 256;
                int row = idx >> 4, part = idx & 15;
                cp16(&Vs[nb][row * 272 + part * 16], Vg + (size_t)row * NA + j0 + part * 8);
            }
            CP_COMMIT();
            CP_WAIT(1);
        } else {
            CP_WAIT(0);
        }
        __syncthreads();

        #pragma unroll
        for (int m = 0; m < 8; m++) {
            // K fragments: 2 ldmatrix.x4
            uint32_t kf[2][4];
            {
                uint32_t a0 = cvta_sh(&Ks[buf][(m * 16 + (lane & 7)) * 80 + (lane >> 3) * 16]);
                LDMX4(kf[0][0], kf[0][1], kf[0][2], kf[0][3], a0);
                LDMX4(kf[1][0], kf[1][1], kf[1][2], kf[1][3], a0 + 8 * 80);
            }

            // S = Q.K^T - ESHIFT (shift folded into accumulator init)
            float s[2][2][4];
            #pragma unroll
            for (int mt = 0; mt < 2; mt++)
                #pragma unroll
                for (int h = 0; h < 2; h++) {
                    float c0 = -ESHIFT, c1 = -ESHIFT, c2 = -ESHIFT, c3 = -ESHIFT;
                    mma16816(c0, c1, c2, c3,
                             qa[mt][0][0], qa[mt][0][1], qa[mt][0][2], qa[mt][0][3],
                             kf[h][0], kf[h][1]);
                    mma16816(c0, c1, c2, c3,
                             qa[mt][1][0], qa[mt][1][1], qa[mt][1][2], qa[mt][1][3],
                             kf[h][2], kf[h][3]);
                    s[mt][h][0] = c0; s[mt][h][1] = c1; s[mt][h][2] = c2; s[mt][h][3] = c3;
                }

            // pack then f16x2 exp2 -> P fragments directly
            uint32_t pa[2][4];
            #pragma unroll
            for (int mt = 0; mt < 2; mt++) {
                pa[mt][0] = h2ex2(pack_h2(s[mt][0][0], s[mt][0][1]));
                pa[mt][1] = h2ex2(pack_h2(s[mt][0][2], s[mt][0][3]));
                pa[mt][2] = h2ex2(pack_h2(s[mt][1][0], s[mt][1][1]));
                pa[mt][3] = h2ex2(pack_h2(s[mt][1][2], s[mt][1][3]));
            }

            // row sums: lacc += P . ones  (tensor pipe, no scalar adds)
            #pragma unroll
            for (int mt = 0; mt < 2; mt++)
                mma16816(lacc[mt][0], lacc[mt][1], lacc[mt][2], lacc[mt][3],
                         pa[mt][0], pa[mt][1], pa[mt][2], pa[mt][3],
                         H2ONES, H2ONES);

            // V fragments: 2 ldmatrix.x4
            uint32_t vf[4][2];
            {
                uint32_t a0 = cvta_sh(&Vs[buf][(((lane >> 4) << 3) + (lane & 7)) * 272
                                               + m * 32 + ((lane >> 3) & 1) * 16]);
                LDMX4(vf[0][0], vf[0][1], vf[1][0], vf[1][1], a0);
                LDMX4(vf[2][0], vf[2][1], vf[3][0], vf[3][1], a0 + 16 * 272);
            }

            // O += P.V
            #pragma unroll
            for (int mt = 0; mt < 2; mt++)
                #pragma unroll
                for (int dt = 0; dt < 4; dt++)
                    mma16816(o[mt][dt][0], o[mt][dt][1], o[mt][dt][2], o[mt][dt][3],
                             pa[mt][0], pa[mt][1], pa[mt][2], pa[mt][3],
                             vf[dt][0], vf[dt][1]);
        }
        __syncthreads();
    }

    // ---- normalize + write AO[b][n][c] fp16 (row sums already per-thread) ----
    const int b = bh >> 5, area = (bh >> 3) & 3, h = bh & 7;
    #pragma unroll
    for (int mt = 0; mt < 2; mt++) {
        const float inv0 = 1.f / lacc[mt][0];
        const float inv1 = 1.f / lacc[mt][2];
        const int nb = area * NA + i0 + mt * 16;
        __half* outp = g_AOh + ((size_t)b * NPIX + nb) * CCH + h * HD;
        #pragma unroll
        for (int dt = 0; dt < 4; dt++) {
            *(__half2*)(outp + (size_t)(gr    ) * CCH + dt * 8 + 2 * tg) =
                __floats2half2_rn(o[mt][dt][0] * inv0, o[mt][dt][1] * inv0);
            *(__half2*)(outp + (size_t)(gr + 8) * CCH + dt * 8 + 2 * tg) =
                __floats2half2_rn(o[mt][dt][2] * inv1, o[mt][dt][3] * inv1);
        }
    }
}

// ---------------------------------------------------------------------------
// proj_out via mma.sync + cp.async double-buffered k-chunks.
// out[b,co,n] = Whp[co,:] . AOh[b,n,:] + shp[co]. CTA 128co x 64n.
// ---------------------------------------------------------------------------
__global__ __launch_bounds__(256) void proj_out_mma(float* __restrict__ out)
{
    __shared__ __align__(16) __half Ws[2][128][72];
    __shared__ __align__(16) __half As[2][64][72];

    const int b   = blockIdx.z;
    const int co0 = blockIdx.y * 128;
    const int n0  = blockIdx.x * 64;
    const int t    = threadIdx.x;
    const int lane = t & 31, wid = t >> 5;
    const int wo = wid >> 1, wn = wid & 1;
    const int gr = lane >> 2, tg = lane & 3;

    const __half* ab = g_AOh + (size_t)b * NPIX * CCH;

    float acc[2][4][4];
    #pragma unroll
    for (int i = 0; i < 2; i++)
        #pragma unroll
        for (int j = 0; j < 4; j++)
            #pragma unroll
            for (int k = 0; k < 4; k++) acc[i][j][k] = 0.f;

    // stage chunk 0 into buf 0
    {
        #pragma unroll
        for (int u = 0; u < 4; u++) {
            int idx = t + u * 256;
            int row = idx >> 3, seg = idx & 7;
            cp16(&Ws[0][row][seg * 8], g_Whp + (size_t)(co0 + row) * 256 + seg * 8);
        }
        #pragma unroll
        for (int u = 0; u < 2; u++) {
            int idx = t + u * 256;
            int row = idx >> 3, seg = idx & 7;
            cp16(&As[0][row][seg * 8], ab + (size_t)(n0 + row) * CCH + seg * 8);
        }
        CP_COMMIT();
    }

    #pragma unroll 1
    for (int it = 0; it < 4; it++) {
        const int buf = it & 1;
        if (it < 3) {
            const int k0 = (it + 1) * 64, nb = buf ^ 1;
            #pragma unroll
            for (int u = 0; u < 4; u++) {
                int idx = t + u * 256;
                int row = idx >> 3, seg = idx & 7;
                cp16(&Ws[nb][row][seg * 8], g_Whp + (size_t)(co0 + row) * 256 + k0 + seg * 8);
            }
            #pragma unroll
            for (int u = 0; u < 2; u++) {
                int idx = t + u * 256;
                int row = idx >> 3, seg = idx & 7;
                cp16(&As[nb][row][seg * 8], ab + (size_t)(n0 + row) * CCH + k0 + seg * 8);
            }
            CP_COMMIT();
            CP_WAIT(1);
        } else {
            CP_WAIT(0);
        }
        __syncthreads();

        #pragma unroll
        for (int k16 = 0; k16 < 4; k16++) {
            uint32_t a[2][4];
            #pragma unroll
            for (int ot = 0; ot < 2; ot++) {
                uint32_t addr = cvta_sh(&Ws[buf][wo * 32 + ot * 16 + (lane & 15)]
                                               [k16 * 16 + ((lane >> 4) << 3)]);
                LDMX4(a[ot][0], a[ot][1], a[ot][2], a[ot][3], addr);
            }
            uint32_t bf[2][4];
            #pragma unroll
            for (int nt = 0; nt < 2; nt++) {
                uint32_t addr = cvta_sh(&As[buf][wn * 32 + nt * 16 + ((lane >> 4) << 3) + (lane & 7)]
                                               [k16 * 16 + (lane & 8)]);
                LDMX4(bf[nt][0], bf[nt][1], bf[nt][2], bf[nt][3], addr);
            }
            #pragma unroll
            for (int ot = 0; ot < 2; ot++)
                #pragma unroll
                for (int nt = 0; nt < 2; nt++)
                    #pragma unroll
                    for (int nh = 0; nh < 2; nh++) {
                        int ni = nt * 2 + nh;
                        mma16816(acc[ot][ni][0], acc[ot][ni][1], acc[ot][ni][2], acc[ot][ni][3],
                                 a[ot][0], a[ot][1], a[ot][2], a[ot][3],
                                 bf[nt][nh * 2], bf[nt][nh * 2 + 1]);
                    }
        }
        __syncthreads();
    }

    #pragma unroll
    for (int ot = 0; ot < 2; ot++) {
        const int co = co0 + wo * 32 + ot * 16 + gr;
        const float sh0 = g_shp[co], sh1 = g_shp[co + 8];
        #pragma unroll
        for (int ni = 0; ni < 4; ni++) {
            int n = n0 + wn * 32 + (ni >> 1) * 16 + (ni & 1) * 8 + 2 * tg;
            float2 r0, r1;
            r0.x = acc[ot][ni][0] + sh0; r0.y = acc[ot][ni][1] + sh0;
            r1.x = acc[ot][ni][2] + sh1; r1.y = acc[ot][ni][3] + sh1;
            *(float2*)(out + ((size_t)(b * CCH + co    )) * NPIX + n) = r0;
            *(float2*)(out + ((size_t)(b * CCH + co + 8)) * NPIX + n) = r1;
        }
    }
}

// ---------------------------------------------------------------------------
extern "C" void kernel_launch(void* const* d_in, const int* in_sizes, int n_in,
                              void* d_out, int out_size)
{
    const float* x    = (const float*)d_in[0];
    const float* w_qk = (const float*)d_in[1];
    const float* g_qk = (const float*)d_in[2];
    const float* b_qk = (const float*)d_in[3];
    const float* m_qk = (const float*)d_in[4];
    const float* v_qk = (const float*)d_in[5];
    const float* w_v  = (const float*)d_in[6];
    const float* g_v  = (const float*)d_in[7];
    const float* b_v  = (const float*)d_in[8];
    const float* m_v  = (const float*)d_in[9];
    const float* v_v  = (const float*)d_in[10];
    const float* w_p  = (const float*)d_in[11];
    const float* g_p  = (const float*)d_in[12];
    const float* b_p  = (const float*)d_in[13];
    const float* m_p  = (const float*)d_in[14];
    const float* v_p  = (const float*)d_in[15];
    float* out = (float*)d_out;

    prep_w<<<1024, 256>>>(w_qk, g_qk, b_qk, m_qk, v_qk,
                          w_v,  g_v,  b_v,  m_v,  v_v,
                          w_p,  g_p,  b_p,  m_p,  v_p);
    prep_x<<<2048, 256>>>(x);
    proj_in_mma<<<dim3(64, 6, BATCH), 256>>>();
    attn_mma<<<dim3(4, 64), 256>>>();
    proj_out_mma<<<dim3(64, 2, BATCH), 256>>>(out);
}

// round 15
// speedup vs baseline: 1.1344x; 1.0796x over previous
#include <cuda_runtime.h>
#include <cuda_fp16.h>
#include <cstdint>

#define BATCH 2
#define CCH   256
#define NPIX  4096      // 64*64
#define BA    8         // BATCH*AREA
#define NA    1024      // NPIX/AREA
#define NH    8
#define HD    32
#define EPS   1e-5f

// scale * log2(e) folded into W_q rows so P = exp2(S - SHIFT)
#define QSCALE (0.17677669529663687f * 1.4426950408889634f)
#define H2ONES   0x3C003C00u   // (1.0, 1.0) fp16x2
#define H2MSHIFT 0xC800C800u   // (-8.0, -8.0) fp16x2  (exp2 shift folded into S acc init)

// Scratch (device globals; no allocation allowed)
__device__ __half g_Qh[BA * NH * NA * HD];    // [bh][i][d]  pre-scaled fp16
__device__ __half g_Kh[BA * NH * NA * HD];    // [bh][j][d]  fp16
__device__ __half g_Vh[BA * NH * HD * NA];    // [bh][d][j]  TRANSPOSED fp16
__device__ __half g_AOh[BATCH * NPIX * CCH];  // [b][n][c]   fp16
__device__ __half g_xh[BATCH * CCH * NPIX];   // [b][c][n]   fp16
__device__ __half g_Wh[768 * 256];            // BN-folded w_qk (Q rows xQSCALE) + w_v
__device__ __half g_Whp[256 * 256];           // BN-folded w_p
__device__ float  g_sh[768];
__device__ float  g_shp[256];

// ---------------------------------------------------------------------------
// PTX helpers
// ---------------------------------------------------------------------------
__device__ __forceinline__ void mma16816(float& c0, float& c1, float& c2, float& c3,
                                         uint32_t a0, uint32_t a1, uint32_t a2, uint32_t a3,
                                         uint32_t b0, uint32_t b1)
{
    asm volatile(
        "mma.sync.aligned.m16n8k16.row.col.f32.f16.f16.f32 "
        "{%0,%1,%2,%3}, {%4,%5,%6,%7}, {%8,%9}, {%0,%1,%2,%3};"
        : "+f"(c0), "+f"(c1), "+f"(c2), "+f"(c3)
        : "r"(a0), "r"(a1), "r"(a2), "r"(a3), "r"(b0), "r"(b1));
}

// f16-accumulator variant: C = 2 packed f16x2 regs (rows gr / gr+8)
__device__ __forceinline__ void mma16816h(uint32_t& c0, uint32_t& c1,
                                          uint32_t a0, uint32_t a1, uint32_t a2, uint32_t a3,
                                          uint32_t b0, uint32_t b1)
{
    asm volatile(
        "mma.sync.aligned.m16n8k16.row.col.f16.f16.f16.f16 "
        "{%0,%1}, {%2,%3,%4,%5}, {%6,%7}, {%0,%1};"
        : "+r"(c0), "+r"(c1)
        : "r"(a0), "r"(a1), "r"(a2), "r"(a3), "r"(b0), "r"(b1));
}

// two exp2 in one MUFU op, result stays packed fp16x2
__device__ __forceinline__ uint32_t h2ex2(uint32_t x) {
    uint32_t r;
    asm("ex2.approx.f16x2 %0, %1;" : "=r"(r) : "r"(x));
    return r;
}

__device__ __forceinline__ uint32_t cvta_sh(const void* p) {
    return (uint32_t)__cvta_generic_to_shared(p);
}

__device__ __forceinline__ void cp16(void* sm, const void* gm) {
    asm volatile("cp.async.cg.shared.global [%0], [%1], 16;"
        :: "r"(cvta_sh(sm)), "l"(gm));
}
#define CP_COMMIT() asm volatile("cp.async.commit_group;")
#define CP_WAIT(n)  asm volatile("cp.async.wait_group %0;" :: "n"(n))

#define LDMX4(r0,r1,r2,r3,addr) \
    asm volatile("ldmatrix.sync.aligned.m8n8.x4.shared.b16 {%0,%1,%2,%3}, [%4];" \
        : "=r"(r0),"=r"(r1),"=r"(r2),"=r"(r3) : "r"(addr))
#define LDMX4T(r0,r1,r2,r3,addr) \
    asm volatile("ldmatrix.sync.aligned.m8n8.x4.trans.shared.b16 {%0,%1,%2,%3}, [%4];" \
        : "=r"(r0),"=r"(r1),"=r"(r2),"=r"(r3) : "r"(addr))

// ---------------------------------------------------------------------------
// Fused prepass: blocks [0,1024) fold BN into weights (fp16 + shift vectors);
// blocks [1024,3072) convert x -> fp16.
// ---------------------------------------------------------------------------
__global__ void prep_all(
    const float* __restrict__ x,
    const float* __restrict__ w_qk, const float* __restrict__ g_qk, const float* __restrict__ b_qk,
    const float* __restrict__ m_qk, const float* __restrict__ v_qk,
    const float* __restrict__ w_v,  const float* __restrict__ g_v,  const float* __restrict__ b_v,
    const float* __restrict__ m_v,  const float* __restrict__ v_v,
    const float* __restrict__ w_p,  const float* __restrict__ g_p,  const float* __restrict__ b_p,
    const float* __restrict__ m_p,  const float* __restrict__ v_p)
{
    if (blockIdx.x >= 1024) {
        const int i = ((blockIdx.x - 1024) * 256 + threadIdx.x) * 4;
        float4 v = *(const float4*)(x + i);
        __half2* d = (__half2*)(g_xh + i);
        d[0] = __floats2half2_rn(v.x, v.y);
        d[1] = __floats2half2_rn(v.z, v.w);
        return;
    }
    const int row = blockIdx.x;
    const int c   = threadIdx.x;
    const float *w, *g, *b, *m, *v;
    __half* dst; float* shd;
    int r; float extra = 1.f;
    if (row < 512) {
        w = w_qk; g = g_qk; b = b_qk; m = m_qk; v = v_qk;
        r = row; dst = g_Wh + (size_t)row * 256; shd = g_sh + row;
        if (row < 256) extra = QSCALE;
    } else if (row < 768) {
        w = w_v; g = g_v; b = b_v; m = m_v; v = v_v;
        r = row - 512; dst = g_Wh + (size_t)row * 256; shd = g_sh + row;
    } else {
        w = w_p; g = g_p; b = b_p; m = m_p; v = v_p;
        r = row - 768; dst = g_Whp + (size_t)r * 256; shd = g_shp + r;
    }
    float s0 = g[r] * rsqrtf(v[r] + EPS);
    dst[c] = __float2half_rn(w[(size_t)r * 256 + c] * s0 * extra);
    if (c == 0) *shd = (b[r] - m[r] * s0) * extra;
}

// ---------------------------------------------------------------------------
// proj_in via mma.sync + cp.async double-buffered k-chunks.
// Y[o,n] = Wh[o,:] . xh[b,:,n] + sh[o], o in [0,768). CTA 128o x 64n.
// ---------------------------------------------------------------------------
__global__ __launch_bounds__(256) void proj_in_mma()
{
    __shared__ __align__(16) __half Ws[2][128][72];
    __shared__ __align__(16) __half Xs[2][64][72];

    const int b  = blockIdx.z;
    const int o0 = blockIdx.y * 128;
    const int n0 = blockIdx.x * 64;
    const int t    = threadIdx.x;
    const int lane = t & 31, wid = t >> 5;
    const int wo = wid >> 1, wn = wid & 1;
    const int gr = lane >> 2, tg = lane & 3;

    const __half* xb = g_xh + (size_t)b * CCH * NPIX;

    float acc[2][4][4];
    #pragma unroll
    for (int i = 0; i < 2; i++)
        #pragma unroll
        for (int j = 0; j < 4; j++)
            #pragma unroll
            for (int k = 0; k < 4; k++) acc[i][j][k] = 0.f;

    // stage chunk 0 into buf 0
    {
        #pragma unroll
        for (int u = 0; u < 4; u++) {
            int idx = t + u * 256;
            int row = idx >> 3, seg = idx & 7;
            cp16(&Ws[0][row][seg * 8], g_Wh + (size_t)(o0 + row) * 256 + seg * 8);
        }
        #pragma unroll
        for (int u = 0; u < 2; u++) {
            int idx = t + u * 256;
            int row = idx >> 3, seg = idx & 7;
            cp16(&Xs[0][row][seg * 8], xb + (size_t)row * NPIX + n0 + seg * 8);
        }
        CP_COMMIT();
    }

    #pragma unroll 1
    for (int it = 0; it < 4; it++) {
        const int buf = it & 1;
        if (it < 3) {
            const int k0 = (it + 1) * 64, nb = buf ^ 1;
            #pragma unroll
            for (int u = 0; u < 4; u++) {
                int idx = t + u * 256;
                int row = idx >> 3, seg = idx & 7;
                cp16(&Ws[nb][row][seg * 8], g_Wh + (size_t)(o0 + row) * 256 + k0 + seg * 8);
            }
            #pragma unroll
            for (int u = 0; u < 2; u++) {
                int idx = t + u * 256;
                int row = idx >> 3, seg = idx & 7;
                cp16(&Xs[nb][row][seg * 8], xb + (size_t)(k0 + row) * NPIX + n0 + seg * 8);
            }
            CP_COMMIT();
            CP_WAIT(1);
        } else {
            CP_WAIT(0);
        }
        __syncthreads();

        #pragma unroll
        for (int k16 = 0; k16 < 4; k16++) {
            uint32_t a[2][4];
            #pragma unroll
            for (int ot = 0; ot < 2; ot++) {
                uint32_t addr = cvta_sh(&Ws[buf][wo * 32 + ot * 16 + (lane & 15)]
                                               [k16 * 16 + ((lane >> 4) << 3)]);
                LDMX4(a[ot][0], a[ot][1], a[ot][2], a[ot][3], addr);
            }
            uint32_t bf[2][4];
            #pragma unroll
            for (int nt = 0; nt < 2; nt++) {
                uint32_t addr = cvta_sh(&Xs[buf][k16 * 16 + (lane & 15)]
                                               [wn * 32 + nt * 16 + ((lane >> 4) << 3)]);
                LDMX4T(bf[nt][0], bf[nt][1], bf[nt][2], bf[nt][3], addr);
            }
            #pragma unroll
            for (int ot = 0; ot < 2; ot++)
                #pragma unroll
                for (int nt = 0; nt < 2; nt++)
                    #pragma unroll
                    for (int nh = 0; nh < 2; nh++) {
                        int ni = nt * 2 + nh;
                        mma16816(acc[ot][ni][0], acc[ot][ni][1], acc[ot][ni][2], acc[ot][ni][3],
                                 a[ot][0], a[ot][1], a[ot][2], a[ot][3],
                                 bf[nt][nh * 2], bf[nt][nh * 2 + 1]);
                    }
        }
        __syncthreads();
    }

    #pragma unroll
    for (int ot = 0; ot < 2; ot++) {
        const int og = o0 + wo * 32 + ot * 16 + gr;
        const float sh0 = g_sh[og], sh1 = g_sh[og + 8];
        if (o0 < 512) {
            __half* dst = (o0 < 256) ? g_Qh : g_Kh;
            const int ob0 = og & 255, ob1 = (og + 8) & 255;
            const int h0 = ob0 >> 5, d0 = ob0 & 31;
            const int h1 = ob1 >> 5, d1 = ob1 & 31;
            #pragma unroll
            for (int ni = 0; ni < 4; ni++) {
                int n  = n0 + wn * 32 + (ni >> 1) * 16 + (ni & 1) * 8 + 2 * tg;
                int ba = b * 4 + (n >> 10), na = n & 1023;
                size_t base = (size_t)(ba * NH) * NA * HD;
                dst[base + ((size_t)h0 * NA + na    ) * HD + d0] = __float2half_rn(acc[ot][ni][0] + sh0);
                dst[base + ((size_t)h0 * NA + na + 1) * HD + d0] = __float2half_rn(acc[ot][ni][1] + sh0);
                dst[base + ((size_t)h1 * NA + na    ) * HD + d1] = __float2half_rn(acc[ot][ni][2] + sh1);
                dst[base + ((size_t)h1 * NA + na + 1) * HD + d1] = __float2half_rn(acc[ot][ni][3] + sh1);
            }
        } else {
            const int oc0 = og - 512, oc1 = og - 512 + 8;
            const int h0 = oc0 >> 5, d0 = oc0 & 31;
            const int h1 = oc1 >> 5, d1 = oc1 & 31;
            #pragma unroll
            for (int ni = 0; ni < 4; ni++) {
                int n  = n0 + wn * 32 + (ni >> 1) * 16 + (ni & 1) * 8 + 2 * tg;
                int ba = b * 4 + (n >> 10), na = n & 1023;
                *(__half2*)&g_Vh[(((size_t)(ba * NH + h0)) * HD + d0) * NA + na] =
                    __floats2half2_rn(acc[ot][ni][0] + sh0, acc[ot][ni][1] + sh0);
                *(__half2*)&g_Vh[(((size_t)(ba * NH + h1)) * HD + d1) * NA + na] =
                    __floats2half2_rn(acc[ot][ni][2] + sh1, acc[ot][ni][3] + sh1);
            }
        }
    }
}

// ---------------------------------------------------------------------------
// Attention: round-8 config + f16-accumulator S-MMA.
// 256 threads = 8 warps x 32 q rows, 128-row KV chunks, ldmatrix frags,
// cp.async double buffer, exp2-shift folded into f16 S acc init (0xC800C800),
// P fragments = h2ex2(S f16 C-frags) with zero cvts, row sums via ones-MMA
// (fp32 acc), PV fp32 acc. Grid (4, 64).
// ---------------------------------------------------------------------------
__global__ __launch_bounds__(256) void attn_mma()
{
    __shared__ __align__(16) unsigned char Ks[2][128 * 80];   // [j][d] pitch 80
    __shared__ __align__(16) unsigned char Vs[2][32 * 272];   // [d][j] pitch 272

    const int t    = threadIdx.x;
    const int wid  = t >> 5;
    const int lane = t & 31;
    const int gr   = lane >> 2;
    const int tg   = lane & 3;
    const int bh   = blockIdx.y;
    const int q0   = blockIdx.x * 256;
    const int i0   = q0 + wid * 32;

    const __half* Qg = g_Qh + ((size_t)bh * NA + i0) * HD;
    const __half* Kg = g_Kh + (size_t)bh * NA * HD;
    const __half* Vg = g_Vh + (size_t)bh * HD * NA;

    // Q A-fragments: 2 m-tiles x 2 k-tiles
    uint32_t qa[2][2][4];
    #pragma unroll
    for (int mt = 0; mt < 2; mt++)
        #pragma unroll
        for (int kt = 0; kt < 2; kt++) {
            qa[mt][kt][0] = *(const uint32_t*)(Qg + (mt * 16 + gr    ) * HD + kt * 16 + 2 * tg    );
            qa[mt][kt][1] = *(const uint32_t*)(Qg + (mt * 16 + gr + 8) * HD + kt * 16 + 2 * tg    );
            qa[mt][kt][2] = *(const uint32_t*)(Qg + (mt * 16 + gr    ) * HD + kt * 16 + 2 * tg + 8);
            qa[mt][kt][3] = *(const uint32_t*)(Qg + (mt * 16 + gr + 8) * HD + kt * 16 + 2 * tg + 8);
        }

    float o[2][4][4];
    #pragma unroll
    for (int mt = 0; mt < 2; mt++)
        #pragma unroll
        for (int dt = 0; dt < 4; dt++)
            #pragma unroll
            for (int c = 0; c < 4; c++) o[mt][dt][c] = 0.f;
    float lacc[2][4];
    #pragma unroll
    for (int mt = 0; mt < 2; mt++)
        #pragma unroll
        for (int c = 0; c < 4; c++) lacc[mt][c] = 0.f;

    // stage tile 0 into buf 0
    {
        #pragma unroll
        for (int u = 0; u < 2; u++) {
            int idx = t + u * 256;
            int row = idx >> 2, part = idx & 3;
            cp16(&Ks[0][row * 80 + part * 16], Kg + (size_t)row * HD + part * 8);
        }
        #pragma unroll
        for (int u = 0; u < 2; u++) {
            int idx = t + u * 256;
            int row = idx >> 4, part = idx & 15;
            cp16(&Vs[0][row * 272 + part * 16], Vg + (size_t)row * NA + part * 8);
        }
        CP_COMMIT();
    }

    #pragma unroll 1
    for (int it = 0; it < 8; it++) {
        const int buf = it & 1;
        if (it < 7) {
            const int j0 = (it + 1) * 128, nb = buf ^ 1;
            #pragma unroll
            for (int u = 0; u < 2; u++) {
                int idx = t + u * 256;
                int row = idx >> 2, part = idx & 3;
                cp16(&Ks[nb][row * 80 + part * 16], Kg + (size_t)(j0 + row) * HD + part * 8);
            }
            #pragma unroll
            for (int u = 0; u < 2; u++) {
                int idx = t + u * 256;
                int row = idx >> 4, part = idx & 15;
                cp16(&Vs[nb][row * 272 + part * 16], Vg + (size_t)row * NA + j0 + part * 8);
            }
            CP_COMMIT();
            CP_WAIT(1);
        } else {
            CP_WAIT(0);
        }
        __syncthreads();

        #pragma unroll
        for (int m = 0; m < 8; m++) {
            // K fragments: 2 ldmatrix.x4
            uint32_t kf[2][4];
            {
                uint32_t a0 = cvta_sh(&Ks[buf][(m * 16 + (lane & 7)) * 80 + (lane >> 3) * 16]);
                LDMX4(kf[0][0], kf[0][1], kf[0][2], kf[0][3], a0);
                LDMX4(kf[1][0], kf[1][1], kf[1][2], kf[1][3], a0 + 8 * 80);
            }

            // S = Q.K^T - 8 in f16 accumulators; P = exp2(S) directly from
            // the packed C fragments (f16 C layout == P A-fragment layout).
            uint32_t pa[2][4];
            #pragma unroll
            for (int mt = 0; mt < 2; mt++) {
                #pragma unroll
                for (int h = 0; h < 2; h++) {
                    uint32_t c0 = H2MSHIFT, c1 = H2MSHIFT;
                    mma16816h(c0, c1,
                              qa[mt][0][0], qa[mt][0][1], qa[mt][0][2], qa[mt][0][3],
                              kf[h][0], kf[h][1]);
                    mma16816h(c0, c1,
                              qa[mt][1][0], qa[mt][1][1], qa[mt][1][2], qa[mt][1][3],
                              kf[h][2], kf[h][3]);
                    pa[mt][h * 2    ] = h2ex2(c0);
                    pa[mt][h * 2 + 1] = h2ex2(c1);
                }
            }

            // row sums: lacc += P . ones  (fp32 acc, tensor pipe)
            #pragma unroll
            for (int mt = 0; mt < 2; mt++)
                mma16816(lacc[mt][0], lacc[mt][1], lacc[mt][2], lacc[mt][3],
                         pa[mt][0], pa[mt][1], pa[mt][2], pa[mt][3],
                         H2ONES, H2ONES);

            // V fragments: 2 ldmatrix.x4
            uint32_t vf[4][2];
            {
                uint32_t a0 = cvta_sh(&Vs[buf][(((lane >> 4) << 3) + (lane & 7)) * 272
                                               + m * 32 + ((lane >> 3) & 1) * 16]);
                LDMX4(vf[0][0], vf[0][1], vf[1][0], vf[1][1], a0);
                LDMX4(vf[2][0], vf[2][1], vf[3][0], vf[3][1], a0 + 16 * 272);
            }

            // O += P.V  (fp32 acc)
            #pragma unroll
            for (int mt = 0; mt < 2; mt++)
                #pragma unroll
                for (int dt = 0; dt < 4; dt++)
                    mma16816(o[mt][dt][0], o[mt][dt][1], o[mt][dt][2], o[mt][dt][3],
                             pa[mt][0], pa[mt][1], pa[mt][2], pa[mt][3],
                             vf[dt][0], vf[dt][1]);
        }
        __syncthreads();
    }

    // ---- normalize + write AO[b][n][c] fp16 (row sums already per-thread) ----
    const int b = bh >> 5, area = (bh >> 3) & 3, h = bh & 7;
    #pragma unroll
    for (int mt = 0; mt < 2; mt++) {
        const float inv0 = 1.f / lacc[mt][0];
        const float inv1 = 1.f / lacc[mt][2];
        const int nb = area * NA + i0 + mt * 16;
        __half* outp = g_AOh + ((size_t)b * NPIX + nb) * CCH + h * HD;
        #pragma unroll
        for (int dt = 0; dt < 4; dt++) {
            *(__half2*)(outp + (size_t)(gr    ) * CCH + dt * 8 + 2 * tg) =
                __floats2half2_rn(o[mt][dt][0] * inv0, o[mt][dt][1] * inv0);
            *(__half2*)(outp + (size_t)(gr + 8) * CCH + dt * 8 + 2 * tg) =
                __floats2half2_rn(o[mt][dt][2] * inv1, o[mt][dt][3] * inv1);
        }
    }
}

// ---------------------------------------------------------------------------
// proj_out via mma.sync + cp.async double-buffered k-chunks.
// out[b,co,n] = Whp[co,:] . AOh[b,n,:] + shp[co]. CTA 128co x 64n.
// ---------------------------------------------------------------------------
__global__ __launch_bounds__(256) void proj_out_mma(float* __restrict__ out)
{
    __shared__ __align__(16) __half Ws[2][128][72];
    __shared__ __align__(16) __half As[2][64][72];

    const int b   = blockIdx.z;
    const int co0 = blockIdx.y * 128;
    const int n0  = blockIdx.x * 64;
    const int t    = threadIdx.x;
    const int lane = t & 31, wid = t >> 5;
    const int wo = wid >> 1, wn = wid & 1;
    const int gr = lane >> 2, tg = lane & 3;

    const __half* ab = g_AOh + (size_t)b * NPIX * CCH;

    float acc[2][4][4];
    #pragma unroll
    for (int i = 0; i < 2; i++)
        #pragma unroll
        for (int j = 0; j < 4; j++)
            #pragma unroll
            for (int k = 0; k < 4; k++) acc[i][j][k] = 0.f;

    // stage chunk 0 into buf 0
    {
        #pragma unroll
        for (int u = 0; u < 4; u++) {
            int idx = t + u * 256;
            int row = idx >> 3, seg = idx & 7;
            cp16(&Ws[0][row][seg * 8], g_Whp + (size_t)(co0 + row) * 256 + seg * 8);
        }
        #pragma unroll
        for (int u = 0; u < 2; u++) {
            int idx = t + u * 256;
            int row = idx >> 3, seg = idx & 7;
            cp16(&As[0][row][seg * 8], ab + (size_t)(n0 + row) * CCH + seg * 8);
        }
        CP_COMMIT();
    }

    #pragma unroll 1
    for (int it = 0; it < 4; it++) {
        const int buf = it & 1;
        if (it < 3) {
            const int k0 = (it + 1) * 64, nb = buf ^ 1;
            #pragma unroll
            for (int u = 0; u < 4; u++) {
                int idx = t + u * 256;
                int row = idx >> 3, seg = idx & 7;
                cp16(&Ws[nb][row][seg * 8], g_Whp + (size_t)(co0 + row) * 256 + k0 + seg * 8);
            }
            #pragma unroll
            for (int u = 0; u < 2; u++) {
                int idx = t + u * 256;
                int row = idx >> 3, seg = idx & 7;
                cp16(&As[nb][row][seg * 8], ab + (size_t)(n0 + row) * CCH + k0 + seg * 8);
            }
            CP_COMMIT();
            CP_WAIT(1);
        } else {
            CP_WAIT(0);
        }
        __syncthreads();

        #pragma unroll
        for (int k16 = 0; k16 < 4; k16++) {
            uint32_t a[2][4];
            #pragma unroll
            for (int ot = 0; ot < 2; ot++) {
                uint32_t addr = cvta_sh(&Ws[buf][wo * 32 + ot * 16 + (lane & 15)]
                                               [k16 * 16 + ((lane >> 4) << 3)]);
                LDMX4(a[ot][0], a[ot][1], a[ot][2], a[ot][3], addr);
            }
            uint32_t bf[2][4];
            #pragma unroll
            for (int nt = 0; nt < 2; nt++) {
                uint32_t addr = cvta_sh(&As[buf][wn * 32 + nt * 16 + ((lane >> 4) << 3) + (lane & 7)]
                                               [k16 * 16 + (lane & 8)]);
                LDMX4(bf[nt][0], bf[nt][1], bf[nt][2], bf[nt][3], addr);
            }
            #pragma unroll
            for (int ot = 0; ot < 2; ot++)
                #pragma unroll
                for (int nt = 0; nt < 2; nt++)
                    #pragma unroll
                    for (int nh = 0; nh < 2; nh++) {
                        int ni = nt * 2 + nh;
                        mma16816(acc[ot][ni][0], acc[ot][ni][1], acc[ot][ni][2], acc[ot][ni][3],
                                 a[ot][0], a[ot][1], a[ot][2], a[ot][3],
                                 bf[nt][nh * 2], bf[nt][nh * 2 + 1]);
                    }
        }
        __syncthreads();
    }

    #pragma unroll
    for (int ot = 0; ot < 2; ot++) {
        const int co = co0 + wo * 32 + ot * 16 + gr;
        const float sh0 = g_shp[co], sh1 = g_shp[co + 8];
        #pragma unroll
        for (int ni = 0; ni < 4; ni++) {
            int n = n0 + wn * 32 + (ni >> 1) * 16 + (ni & 1) * 8 + 2 * tg;
            float2 r0, r1;
            r0.x = acc[ot][ni][0] + sh0; r0.y = acc[ot][ni][1] + sh0;
            r1.x = acc[ot][ni][2] + sh1; r1.y = acc[ot][ni][3] + sh1;
            *(float2*)(out + ((size_t)(b * CCH + co    )) * NPIX + n) = r0;
            *(float2*)(out + ((size_t)(b * CCH + co + 8)) * NPIX + n) = r1;
        }
    }
}

// ---------------------------------------------------------------------------
extern "C" void kernel_launch(void* const* d_in, const int* in_sizes, int n_in,
                              void* d_out, int out_size)
{
    const float* x    = (const float*)d_in[0];
    const float* w_qk = (const float*)d_in[1];
    const float* g_qk = (const float*)d_in[2];
    const float* b_qk = (const float*)d_in[3];
    const float* m_qk = (const float*)d_in[4];
    const float* v_qk = (const float*)d_in[5];
    const float* w_v  = (const float*)d_in[6];
    const float* g_v  = (const float*)d_in[7];
    const float* b_v  = (const float*)d_in[8];
    const float* m_v  = (const float*)d_in[9];
    const float* v_v  = (const float*)d_in[10];
    const float* w_p  = (const float*)d_in[11];
    const float* g_p  = (const float*)d_in[12];
    const float* b_p  = (const float*)d_in[13];
    const float* m_p  = (const float*)d_in[14];
    const float* v_p  = (const float*)d_in[15];
    float* out = (float*)d_out;

    prep_all<<<3072, 256>>>(x,
                            w_qk, g_qk, b_qk, m_qk, v_qk,
                            w_v,  g_v,  b_v,  m_v,  v_v,
                            w_p,  g_p,  b_p,  m_p,  v_p);
    proj_in_mma<<<dim3(64, 6, BATCH), 256>>>();
    attn_mma<<<dim3(4, 64), 256>>>();
    proj_out_mma<<<dim3(64, 2, BATCH), 256>>>(out);
}